// round 15
// baseline (speedup 1.0000x reference)
#include <cuda_runtime.h>
#include <cstdint>
#include <math.h>

#define EPSF 1e-6f
#define WARPS 8

// Padded node table: up to 131072 nodes * 2 float4 = 4 MB static scratch.
__device__ float4 g_npad[131072 * 2];

// Vectorized pad: coalesced float loads -> smem -> coalesced STG.128 writes.
__global__ __launch_bounds__(256)
void pad_nodes_kernel(const float* __restrict__ nodes, int n_nodes) {
    __shared__ float st[1792];   // 256 nodes * 7 floats
    int base = blockIdx.x * 256;
    int cnt  = n_nodes - base;
    if (cnt <= 0) return;
    if (cnt > 256) cnt = 256;
    for (int k = threadIdx.x; k < cnt * 7; k += 256)
        st[k] = nodes[(size_t)base * 7 + k];
    __syncthreads();
    int t = threadIdx.x;
    if (t < cnt) {
        const float* p = st + t * 7;
        int i = base + t;
        g_npad[i * 2 + 0] = make_float4(p[0], p[1], p[2], p[3]);
        g_npad[i * 2 + 1] = make_float4(p[4], p[5], p[6], 0.0f);
    }
}

__device__ __forceinline__ float3 f3cross(float3 a, float3 b) {
    return make_float3(a.y * b.z - a.z * b.y,
                       a.z * b.x - a.x * b.z,
                       a.x * b.y - a.y * b.x);
}

__device__ __forceinline__ float3 qrot(float4 q, float3 v) {
    float3 u = make_float3(q.x, q.y, q.z);
    float3 t = f3cross(u, v);
    t.x *= 2.0f; t.y *= 2.0f; t.z *= 2.0f;
    float3 c = f3cross(u, t);
    return make_float3(v.x + q.w * t.x + c.x,
                       v.y + q.w * t.y + c.y,
                       v.z + q.w * t.z + c.z);
}

__device__ __forceinline__ float4 qmul(float4 a, float4 b) {
    return make_float4(
        a.w * b.x + a.x * b.w + a.y * b.z - a.z * b.y,
        a.w * b.y - a.x * b.z + a.y * b.w + a.z * b.x,
        a.w * b.z + a.x * b.y - a.y * b.x + a.z * b.w,
        a.w * b.w - a.x * b.x - a.y * b.y - a.z * b.z);
}

// Branchless atan2(y, x) for y >= 0. Max abs error ~1e-5 rad (budget 1e-3).
__device__ __forceinline__ float fast_atan2_pos(float y, float x) {
    float ax = fabsf(x);
    float mn = fminf(ax, y), mx = fmaxf(ax, y);
    float t  = __fdividef(mn, mx);
    float t2 = t * t;
    float p  = fmaf(t2, fmaf(t2, fmaf(t2, fmaf(t2,
                0.0208351f, -0.085133f), 0.180141f), -0.3302995f), 0.9998660f);
    float at = p * t;
    at = (y > ax)    ? (1.57079632679f - at) : at;
    at = (x < 0.0f)  ? (3.14159265359f - at) : at;
    return at;
}

// Full per-edge SE(3) relative-pose error + log map (algebraically reduced).
__device__ __forceinline__ void edge_error(
    float p0, float p1, float p2, float p3, float p4, float p5, float p6,
    float4 n1a, float4 n1b, float4 n2a, float4 n2b,
    float& r0, float& r1, float& r2, float& r3, float& r4, float& r5)
{
    float3 t1 = make_float3(n1a.x, n1a.y, n1a.z);
    float4 q1 = make_float4(n1a.w, n1b.x, n1b.y, n1b.z);
    float3 t2 = make_float3(n2a.x, n2a.y, n2a.z);
    float4 q2 = make_float4(n2a.w, n2b.x, n2b.y, n2b.z);

    // qa = conj(pose.q);  t_B = qrot(qa, t2 - tp)
    float4 qa = make_float4(-p3, -p4, -p5, p6);
    float3 d  = make_float3(t2.x - p0, t2.y - p1, t2.z - p2);
    float3 tb = qrot(qa, d);

    // q_E = (qa * q2) * conj(q1);  t_E = t_B - qrot(q_E, t1)
    float4 qb = qmul(qa, q2);
    float4 qc = make_float4(-q1.x, -q1.y, -q1.z, q1.w);
    float4 qe = qmul(qb, qc);
    float3 re = qrot(qe, t1);
    float3 te = make_float3(tb.x - re.x, tb.y - re.y, tb.z - re.z);

    // se3_log with |qe| == 1 (exact trig elimination)
    float nn2 = qe.x * qe.x + qe.y * qe.y + qe.z * qe.z;
    float nn  = sqrtf(nn2);
    float theta, scale;
    if (nn > EPSF) {
        theta = 2.0f * fast_atan2_pos(nn, qe.w);
        scale = __fdividef(theta, nn);
    } else {
        float dw = (fabsf(qe.w) > EPSF) ? qe.w : 1.0f;
        scale = __fdividef(2.0f, dw);
        theta = fabsf(scale) * nn;   // tiny
    }
    float c;
    if (theta < EPSF) {
        c = 1.0f / 12.0f;
    } else {
        c = __fdividef(1.0f, theta * theta)
          - qe.w * __fdividef(0.5f, nn * theta);
    }

    float3 phi = make_float3(qe.x * scale, qe.y * scale, qe.z * scale);
    float3 pxt  = f3cross(phi, te);
    float3 ppxt = f3cross(phi, pxt);
    r0 = te.x - 0.5f * pxt.x + c * ppxt.x;
    r1 = te.y - 0.5f * pxt.y + c * ppxt.y;
    r2 = te.z - 0.5f * pxt.z + c * ppxt.z;
    r3 = phi.x; r4 = phi.y; r5 = phi.z;
}

__device__ __forceinline__ float4 shflx1(float4 v) {
    float4 r;
    r.x = __shfl_xor_sync(0xffffffffu, v.x, 1);
    r.y = __shfl_xor_sync(0xffffffffu, v.y, 1);
    r.z = __shfl_xor_sync(0xffffffffu, v.z, 1);
    r.w = __shfl_xor_sync(0xffffffffu, v.w, 1);
    return r;
}
__device__ __forceinline__ float4 sel4(bool c, float4 a, float4 b) {
    return make_float4(c ? a.x : b.x, c ? a.y : b.y,
                       c ? a.z : b.z, c ? a.w : b.w);
}

__global__ __launch_bounds__(256)
void pose_graph_kernel(const int* __restrict__ edges,
                       const float* __restrict__ poses,
                       float* __restrict__ out,
                       int n_edges, int n_nodes)
{
    __shared__ float sp[WARPS][224];   // pose staging: 32 edges * 7 floats
    __shared__ float so[WARPS][192];   // output AoS staging: 32 edges * 6 floats

    const int warp   = threadIdx.x >> 5;
    const int lane   = threadIdx.x & 31;
    const int gwarp  = blockIdx.x * WARPS + warp;
    const int nwarps = gridDim.x * WARPS;
    const int ntiles = (n_edges + 31) >> 5;

    const int h  = lane & 1;
    const int nl = lane >> 1;
    const int m  = (h << 4) | nl;      // permuted edge slot this lane computes
    const int2* E = (const int2*)edges;

    // prefetch edge pair for the first tile (full tiles only)
    int t = gwarp;
    int2 v = make_int2(0, 0);
    if (t < ntiles && t * 32 + 32 <= n_edges) v = __ldg(E + (size_t)t * 32 + lane);

    for (; t < ntiles; t += nwarps) {
        const int ew0 = t * 32;
        const int tn  = t + nwarps;
        const bool nfull = (tn < ntiles) && (tn * 32 + 32 <= n_edges);
        int2 vnext = make_int2(0, 0);
        if (nfull) vnext = __ldg(E + (size_t)tn * 32 + lane);  // hide DRAM latency

        if (ew0 + 32 <= n_edges) {
            // ================= fast, warp-autonomous path =================
            int i1 = min(max(v.x, 0), n_nodes - 1);
            int i2 = min(max(v.y, 0), n_nodes - 1);

            // pose stage: warp-wide LDG.128 -> STS.128
            const float4* P4 = (const float4*)(poses + (size_t)ew0 * 7);
            float4 pa = __ldg(P4 + lane);
            ((float4*)&sp[warp][0])[lane] = pa;
            if (lane < 24) {
                float4 pb = __ldg(P4 + 32 + lane);
                ((float4*)&sp[warp][0])[32 + lane] = pb;
            }

            // cooperative gather: lane pairs fetch the two 16B halves of one
            // node (same 128B line) -> 16 lines per LDG.128, 4 instructions
            int idx0 = __shfl_sync(0xffffffffu, i1, nl);
            int idx1 = __shfl_sync(0xffffffffu, i1, 16 | nl);
            int idx2 = __shfl_sync(0xffffffffu, i2, nl);
            int idx3 = __shfl_sync(0xffffffffu, i2, 16 | nl);
            float4 g0 = __ldg(&g_npad[idx0 * 2 + h]);
            float4 g1 = __ldg(&g_npad[idx1 * 2 + h]);
            float4 g2 = __ldg(&g_npad[idx2 * 2 + h]);
            float4 g3 = __ldg(&g_npad[idx3 * 2 + h]);

            // butterfly exchange with pre-selected operand: the consumer of
            // this lane pair's data IS the pair itself.
            float4 recv1 = shflx1(sel4(h == 0, g1, g0));
            float4 recv2 = shflx1(sel4(h == 0, g3, g2));
            float4 n1a = sel4(h == 0, g0, recv1);   // half0: t0 t1 t2 q0
            float4 n1b = sel4(h == 0, recv1, g1);   // half1: q1 q2 q3 --
            float4 n2a = sel4(h == 0, g2, recv2);
            float4 n2b = sel4(h == 0, recv2, g3);

            __syncwarp();              // pose STS visible warp-wide

            float p0 = sp[warp][m * 7 + 0], p1 = sp[warp][m * 7 + 1];
            float p2 = sp[warp][m * 7 + 2], p3 = sp[warp][m * 7 + 3];
            float p4 = sp[warp][m * 7 + 4], p5 = sp[warp][m * 7 + 5];
            float p6 = sp[warp][m * 7 + 6];

            float r0, r1, r2, r3, r4, r5;
            edge_error(p0, p1, p2, p3, p4, p5, p6, n1a, n1b, n2a, n2b,
                       r0, r1, r2, r3, r4, r5);

            // AoS staging into dedicated so buffer via STS.64
            float2* f2 = (float2*)&so[warp][0];
            f2[m * 3 + 0] = make_float2(r0, r1);
            f2[m * 3 + 1] = make_float2(r2, r3);
            f2[m * 3 + 2] = make_float2(r4, r5);
            __syncwarp();

            // contiguous LDS.128 readback + streaming STG.128
            float4* O4 = (float4*)(out + (size_t)ew0 * 6);
            const float4* S4 = (const float4*)&so[warp][0];
            __stwt(&O4[lane], S4[lane]);
            if (lane < 16) __stwt(&O4[32 + lane], S4[32 + lane]);
            __syncwarp();              // so/sp safe to reuse next iteration
        } else {
            // ================= scalar tail path =================
            int e = ew0 + lane;
            if (e < n_edges) {
                int2 vi = __ldg((const int2*)edges + e);
                int i1 = min(max(vi.x, 0), n_nodes - 1);
                int i2 = min(max(vi.y, 0), n_nodes - 1);
                const float* P = poses + (size_t)e * 7;
                float4 n1a = __ldg(&g_npad[i1 * 2 + 0]), n1b = __ldg(&g_npad[i1 * 2 + 1]);
                float4 n2a = __ldg(&g_npad[i2 * 2 + 0]), n2b = __ldg(&g_npad[i2 * 2 + 1]);
                float r0, r1, r2, r3, r4, r5;
                edge_error(P[0], P[1], P[2], P[3], P[4], P[5], P[6],
                           n1a, n1b, n2a, n2b, r0, r1, r2, r3, r4, r5);
                float* O = out + (size_t)e * 6;
                O[0] = r0; O[1] = r1; O[2] = r2; O[3] = r3; O[4] = r4; O[5] = r5;
            }
        }
        v = vnext;
    }
}

extern "C" void kernel_launch(void* const* d_in, const int* in_sizes, int n_in,
                              void* d_out, int out_size)
{
    // Identify inputs by size: nodes smallest, poses largest, edges remaining.
    int ie = 0, ip = 1, in_ = 2;
    {
        long s0 = in_sizes[0], s1 = in_sizes[1], s2 = in_sizes[2];
        in_ = (s0 <= s1 && s0 <= s2) ? 0 : (s1 <= s0 && s1 <= s2) ? 1 : 2;
        ip  = (s0 >= s1 && s0 >= s2) ? 0 : (s1 >= s0 && s1 >= s2) ? 1 : 2;
        ie  = 3 - in_ - ip;
    }

    const int*   edges = (const int*)d_in[ie];
    const float* poses = (const float*)d_in[ip];
    const float* nodes = (const float*)d_in[in_];
    float*       out   = (float*)d_out;

    int n_edges = in_sizes[ie] / 2;
    int n_nodes = in_sizes[in_] / 7;
    if (n_nodes > 131072) n_nodes = 131072;  // static scratch bound

    pad_nodes_kernel<<<(n_nodes + 255) / 256, 256>>>(nodes, n_nodes);

    // persistent one-wave grid: 8 blocks/SM * 148 SMs
    int ntiles = (n_edges + 31) / 32;
    int blocks = 1184;
    int maxb   = (ntiles + WARPS - 1) / WARPS;
    if (blocks > maxb) blocks = maxb;
    pose_graph_kernel<<<blocks, 256>>>(edges, poses, out, n_edges, n_nodes);
}

// round 16
// speedup vs baseline: 1.1159x; 1.1159x over previous
#include <cuda_runtime.h>
#include <cstdint>
#include <math.h>

#define EPSF 1e-6f
#define WARPS 8

// Padded node table: up to 131072 nodes * 2 float4 = 4 MB static scratch.
__device__ float4 g_npad[131072 * 2];

// Vectorized pad: coalesced float loads -> smem -> coalesced STG.128 writes.
// Fires the PDL trigger after its writes so the main kernel (launched with
// programmatic serialization) can begin its prologue early.
__global__ __launch_bounds__(256)
void pad_nodes_kernel(const float* __restrict__ nodes, int n_nodes) {
    __shared__ float st[1792];   // 256 nodes * 7 floats
    int base = blockIdx.x * 256;
    int cnt  = n_nodes - base;
    if (cnt > 0) {
        if (cnt > 256) cnt = 256;
        for (int k = threadIdx.x; k < cnt * 7; k += 256)
            st[k] = nodes[(size_t)base * 7 + k];
        __syncthreads();
        int t = threadIdx.x;
        if (t < cnt) {
            const float* p = st + t * 7;
            int i = base + t;
            g_npad[i * 2 + 0] = make_float4(p[0], p[1], p[2], p[3]);
            g_npad[i * 2 + 1] = make_float4(p[4], p[5], p[6], 0.0f);
        }
    }
#if __CUDA_ARCH__ >= 900
    cudaTriggerProgrammaticLaunchCompletion();
#endif
}

__device__ __forceinline__ float3 f3cross(float3 a, float3 b) {
    return make_float3(a.y * b.z - a.z * b.y,
                       a.z * b.x - a.x * b.z,
                       a.x * b.y - a.y * b.x);
}

__device__ __forceinline__ float3 qrot(float4 q, float3 v) {
    float3 u = make_float3(q.x, q.y, q.z);
    float3 t = f3cross(u, v);
    t.x *= 2.0f; t.y *= 2.0f; t.z *= 2.0f;
    float3 c = f3cross(u, t);
    return make_float3(v.x + q.w * t.x + c.x,
                       v.y + q.w * t.y + c.y,
                       v.z + q.w * t.z + c.z);
}

__device__ __forceinline__ float4 qmul(float4 a, float4 b) {
    return make_float4(
        a.w * b.x + a.x * b.w + a.y * b.z - a.z * b.y,
        a.w * b.y - a.x * b.z + a.y * b.w + a.z * b.x,
        a.w * b.z + a.x * b.y - a.y * b.x + a.z * b.w,
        a.w * b.w - a.x * b.x - a.y * b.y - a.z * b.z);
}

// Branchless atan2(y, x) for y >= 0. Max abs error ~1e-5 rad (budget 1e-3).
__device__ __forceinline__ float fast_atan2_pos(float y, float x) {
    float ax = fabsf(x);
    float mn = fminf(ax, y), mx = fmaxf(ax, y);
    float t  = __fdividef(mn, mx);
    float t2 = t * t;
    float p  = fmaf(t2, fmaf(t2, fmaf(t2, fmaf(t2,
                0.0208351f, -0.085133f), 0.180141f), -0.3302995f), 0.9998660f);
    float at = p * t;
    at = (y > ax)    ? (1.57079632679f - at) : at;
    at = (x < 0.0f)  ? (3.14159265359f - at) : at;
    return at;
}

// Full per-edge SE(3) relative-pose error + log map (algebraically reduced).
__device__ __forceinline__ void edge_error(
    float p0, float p1, float p2, float p3, float p4, float p5, float p6,
    float4 n1a, float4 n1b, float4 n2a, float4 n2b,
    float& r0, float& r1, float& r2, float& r3, float& r4, float& r5)
{
    float3 t1 = make_float3(n1a.x, n1a.y, n1a.z);
    float4 q1 = make_float4(n1a.w, n1b.x, n1b.y, n1b.z);
    float3 t2 = make_float3(n2a.x, n2a.y, n2a.z);
    float4 q2 = make_float4(n2a.w, n2b.x, n2b.y, n2b.z);

    // qa = conj(pose.q);  t_B = qrot(qa, t2 - tp)
    float4 qa = make_float4(-p3, -p4, -p5, p6);
    float3 d  = make_float3(t2.x - p0, t2.y - p1, t2.z - p2);
    float3 tb = qrot(qa, d);

    // q_E = (qa * q2) * conj(q1);  t_E = t_B - qrot(q_E, t1)
    float4 qb = qmul(qa, q2);
    float4 qc = make_float4(-q1.x, -q1.y, -q1.z, q1.w);
    float4 qe = qmul(qb, qc);
    float3 re = qrot(qe, t1);
    float3 te = make_float3(tb.x - re.x, tb.y - re.y, tb.z - re.z);

    // se3_log with |qe| == 1 (exact trig elimination)
    float nn2 = qe.x * qe.x + qe.y * qe.y + qe.z * qe.z;
    float nn  = sqrtf(nn2);
    float theta, scale;
    if (nn > EPSF) {
        theta = 2.0f * fast_atan2_pos(nn, qe.w);
        scale = __fdividef(theta, nn);
    } else {
        float dw = (fabsf(qe.w) > EPSF) ? qe.w : 1.0f;
        scale = __fdividef(2.0f, dw);
        theta = fabsf(scale) * nn;   // tiny
    }
    float c;
    if (theta < EPSF) {
        c = 1.0f / 12.0f;
    } else {
        c = __fdividef(1.0f, theta * theta)
          - qe.w * __fdividef(0.5f, nn * theta);
    }

    float3 phi = make_float3(qe.x * scale, qe.y * scale, qe.z * scale);
    float3 pxt  = f3cross(phi, te);
    float3 ppxt = f3cross(phi, pxt);
    r0 = te.x - 0.5f * pxt.x + c * ppxt.x;
    r1 = te.y - 0.5f * pxt.y + c * ppxt.y;
    r2 = te.z - 0.5f * pxt.z + c * ppxt.z;
    r3 = phi.x; r4 = phi.y; r5 = phi.z;
}

__device__ __forceinline__ float4 shflx1(float4 v) {
    float4 r;
    r.x = __shfl_xor_sync(0xffffffffu, v.x, 1);
    r.y = __shfl_xor_sync(0xffffffffu, v.y, 1);
    r.z = __shfl_xor_sync(0xffffffffu, v.z, 1);
    r.w = __shfl_xor_sync(0xffffffffu, v.w, 1);
    return r;
}
__device__ __forceinline__ float4 sel4(bool c, float4 a, float4 b) {
    return make_float4(c ? a.x : b.x, c ? a.y : b.y,
                       c ? a.z : b.z, c ? a.w : b.w);
}

__global__ __launch_bounds__(256)
void pose_graph_kernel(const int* __restrict__ edges,
                       const float* __restrict__ poses,
                       float* __restrict__ out,
                       int n_edges, int n_nodes)
{
    __shared__ float sp[WARPS][224];   // pose staging: 32 edges * 7 floats
    __shared__ float so[WARPS][192];   // output AoS staging: 32 edges * 6 floats

    const int warp = threadIdx.x >> 5;
    const int lane = threadIdx.x & 31;
    const int ew0  = blockIdx.x * 256 + warp * 32;   // first edge of this warp
    const int e    = ew0 + lane;

    if (ew0 + 32 <= n_edges) {
        // ========== prologue: independent of g_npad (runs pre-dependency) ===
        int2 vi = __ldg((const int2*)edges + e);
        int i1 = min(max(vi.x, 0), n_nodes - 1);
        int i2 = min(max(vi.y, 0), n_nodes - 1);

        // pose stage: warp-wide LDG.128 -> STS.128
        const float4* P4 = (const float4*)(poses + (size_t)ew0 * 7);
        float4 pa = __ldg(P4 + lane);
        ((float4*)&sp[warp][0])[lane] = pa;
        if (lane < 24) {
            float4 pb = __ldg(P4 + 32 + lane);
            ((float4*)&sp[warp][0])[32 + lane] = pb;
        }

        // wait for pad kernel completion (PDL dependency)
#if __CUDA_ARCH__ >= 900
        cudaGridDependencySynchronize();
#endif

        // cooperative gather: lane pairs fetch the two 16B halves of one node
        // (same 128B line) -> 16 lines per LDG.128, 4 instructions total
        const int h  = lane & 1;
        const int nl = lane >> 1;
        int idx0 = __shfl_sync(0xffffffffu, i1, nl);        // node1, slots  0..15
        int idx1 = __shfl_sync(0xffffffffu, i1, 16 | nl);   // node1, slots 16..31
        int idx2 = __shfl_sync(0xffffffffu, i2, nl);        // node2, slots  0..15
        int idx3 = __shfl_sync(0xffffffffu, i2, 16 | nl);   // node2, slots 16..31
        float4 g0 = __ldg(&g_npad[idx0 * 2 + h]);
        float4 g1 = __ldg(&g_npad[idx1 * 2 + h]);
        float4 g2 = __ldg(&g_npad[idx2 * 2 + h]);
        float4 g3 = __ldg(&g_npad[idx3 * 2 + h]);

        // butterfly exchange with pre-selected operand: the consumer of this
        // lane pair's data IS the pair itself. Lane l computes edge
        // m = 16*(l&1) + (l>>1).
        float4 recv1 = shflx1(sel4(h == 0, g1, g0));
        float4 recv2 = shflx1(sel4(h == 0, g3, g2));
        float4 n1a = sel4(h == 0, g0, recv1);   // half0: t0 t1 t2 q0
        float4 n1b = sel4(h == 0, recv1, g1);   // half1: q1 q2 q3 --
        float4 n2a = sel4(h == 0, g2, recv2);
        float4 n2b = sel4(h == 0, recv2, g3);

        const int m = (h << 4) | nl;   // permuted edge slot this lane computes
        __syncwarp();                  // pose STS visible warp-wide

        float p0 = sp[warp][m * 7 + 0], p1 = sp[warp][m * 7 + 1];
        float p2 = sp[warp][m * 7 + 2], p3 = sp[warp][m * 7 + 3];
        float p4 = sp[warp][m * 7 + 4], p5 = sp[warp][m * 7 + 5];
        float p6 = sp[warp][m * 7 + 6];

        float r0, r1, r2, r3, r4, r5;
        edge_error(p0, p1, p2, p3, p4, p5, p6, n1a, n1b, n2a, n2b,
                   r0, r1, r2, r3, r4, r5);

        // AoS staging into dedicated so buffer via STS.64
        float2* f2 = (float2*)&so[warp][0];   // 96 float2 = 32 edges * 6 floats AoS
        f2[m * 3 + 0] = make_float2(r0, r1);
        f2[m * 3 + 1] = make_float2(r2, r3);
        f2[m * 3 + 2] = make_float2(r4, r5);
        __syncwarp();

        // contiguous LDS.128 readback + streaming STG.128: 48 float4 per warp
        float4* O4 = (float4*)(out + (size_t)ew0 * 6);
        const float4* S4 = (const float4*)&so[warp][0];
        __stwt(&O4[lane], S4[lane]);
        if (lane < 16) __stwt(&O4[32 + lane], S4[32 + lane]);
    } else if (e < n_edges) {
        // ================= scalar tail path =================
#if __CUDA_ARCH__ >= 900
        cudaGridDependencySynchronize();
#endif
        int2 vi = __ldg((const int2*)edges + e);
        int i1 = min(max(vi.x, 0), n_nodes - 1);
        int i2 = min(max(vi.y, 0), n_nodes - 1);
        const float* P = poses + (size_t)e * 7;
        float4 n1a = __ldg(&g_npad[i1 * 2 + 0]), n1b = __ldg(&g_npad[i1 * 2 + 1]);
        float4 n2a = __ldg(&g_npad[i2 * 2 + 0]), n2b = __ldg(&g_npad[i2 * 2 + 1]);
        float r0, r1, r2, r3, r4, r5;
        edge_error(P[0], P[1], P[2], P[3], P[4], P[5], P[6],
                   n1a, n1b, n2a, n2b, r0, r1, r2, r3, r4, r5);
        float* O = out + (size_t)e * 6;
        O[0] = r0; O[1] = r1; O[2] = r2; O[3] = r3; O[4] = r4; O[5] = r5;
    } else {
#if __CUDA_ARCH__ >= 900
        cudaGridDependencySynchronize();
#endif
    }
}

extern "C" void kernel_launch(void* const* d_in, const int* in_sizes, int n_in,
                              void* d_out, int out_size)
{
    // Identify inputs by size: nodes smallest, poses largest, edges remaining.
    int ie = 0, ip = 1, in_ = 2;
    {
        long s0 = in_sizes[0], s1 = in_sizes[1], s2 = in_sizes[2];
        in_ = (s0 <= s1 && s0 <= s2) ? 0 : (s1 <= s0 && s1 <= s2) ? 1 : 2;
        ip  = (s0 >= s1 && s0 >= s2) ? 0 : (s1 >= s0 && s1 >= s2) ? 1 : 2;
        ie  = 3 - in_ - ip;
    }

    const int*   edges = (const int*)d_in[ie];
    const float* poses = (const float*)d_in[ip];
    const float* nodes = (const float*)d_in[in_];
    float*       out   = (float*)d_out;

    int n_edges = in_sizes[ie] / 2;
    int n_nodes = in_sizes[in_] / 7;
    if (n_nodes > 131072) n_nodes = 131072;  // static scratch bound

    pad_nodes_kernel<<<(n_nodes + 255) / 256, 256>>>(nodes, n_nodes);

    // Main kernel with Programmatic Dependent Launch: overlaps its launch +
    // edge/pose prologue with the pad kernel's tail.
    int blocks = (n_edges + 255) / 256;
    cudaLaunchConfig_t cfg = {};
    cfg.gridDim  = dim3(blocks, 1, 1);
    cfg.blockDim = dim3(256, 1, 1);
    cudaLaunchAttribute attrs[1];
    attrs[0].id = cudaLaunchAttributeProgrammaticStreamSerialization;
    attrs[0].val.programmaticStreamSerializationAllowed = 1;
    cfg.attrs = attrs;
    cfg.numAttrs = 1;
    cudaError_t err = cudaLaunchKernelEx(&cfg, pose_graph_kernel,
                                         edges, poses, out, n_edges, n_nodes);
    if (err != cudaSuccess) {
        // Fallback: plain launch (normal stream ordering, still correct)
        pose_graph_kernel<<<blocks, 256>>>(edges, poses, out, n_edges, n_nodes);
    }
}